// round 6
// baseline (speedup 1.0000x reference)
#include <cuda_runtime.h>
#include <cuda_bf16.h>
#include <cuda_fp16.h>
#include <cstdint>

#define BB 4
#define NN 4096
#define DD 128
#define TT 128
#define HH 4
#define HDIM 32
#define M_ROWS (BB*NN)          // 16384
#define SCALE 0.17677669529663687f
#define EXC (SCALE * 1.4426950408889634f)   // scale * log2(e), folded into Q

// ---------------- scratch ----------------
__device__ float          g_tparams[BB*2*DD];
__device__ float          g_bfused[2*DD];             // fused bias b1@Wg+bg
__device__ float          g_x2[M_ROWS*DD];            // fp32 residual
__device__ __nv_bfloat16  g_bf1[M_ROWS*DD];
__device__ __nv_bfloat16  g_bf2[M_ROWS*DD];
__device__ __half         g_q[M_ROWS*DD];
__device__ __half         g_k[M_ROWS*DD];
__device__ __half         g_v[M_ROWS*DD];
__device__ unsigned       g_adjbits[NN*(NN/32)];      // 2 MB bitmask
__device__ __nv_bfloat16  g_wb[131072];               // pre-converted weights

// weight offsets in g_wb
#define OWG 0          // fused W1@Wg  [128][256]
#define OW2 32768
#define OWQ 49152
#define OWK 65536
#define OWV 81920
#define OWO 98304

// ---------------- helpers ----------------
__device__ __forceinline__ unsigned packbf(float x, float y) {
    __nv_bfloat162 h = __floats2bfloat162_rn(x, y);
    return *reinterpret_cast<unsigned*>(&h);
}
__device__ __forceinline__ unsigned packh(float x, float y) {
    __half2 h = __floats2half2_rn(x, y);
    return *reinterpret_cast<unsigned*>(&h);
}

__device__ __forceinline__ void mma16816(float* c, const unsigned* a, unsigned b0, unsigned b1) {
    asm volatile(
        "mma.sync.aligned.m16n8k16.row.col.f32.bf16.bf16.f32 "
        "{%0,%1,%2,%3}, {%4,%5,%6,%7}, {%8,%9}, {%0,%1,%2,%3};"
        : "+f"(c[0]), "+f"(c[1]), "+f"(c[2]), "+f"(c[3])
        : "r"(a[0]), "r"(a[1]), "r"(a[2]), "r"(a[3]), "r"(b0), "r"(b1));
}
__device__ __forceinline__ void mma16816h(float* c, const unsigned* a, unsigned b0, unsigned b1) {
    asm volatile(
        "mma.sync.aligned.m16n8k16.row.col.f32.f16.f16.f32 "
        "{%0,%1,%2,%3}, {%4,%5,%6,%7}, {%8,%9}, {%0,%1,%2,%3};"
        : "+f"(c[0]), "+f"(c[1]), "+f"(c[2]), "+f"(c[3])
        : "r"(a[0]), "r"(a[1]), "r"(a[2]), "r"(a[3]), "r"(b0), "r"(b1));
}
// f16-accumulator QK mma: D = 2 regs of f16x2, directly exp-input / PV-A layout
__device__ __forceinline__ void mma16816hh(unsigned* c, const unsigned* a, unsigned b0, unsigned b1) {
    asm volatile(
        "mma.sync.aligned.m16n8k16.row.col.f16.f16.f16.f16 "
        "{%0,%1}, {%2,%3,%4,%5}, {%6,%7}, {%0,%1};"
        : "+r"(c[0]), "+r"(c[1])
        : "r"(a[0]), "r"(a[1]), "r"(a[2]), "r"(a[3]), "r"(b0), "r"(b1));
}
__device__ __forceinline__ unsigned ex2p(unsigned s) {
    unsigned r;
    asm("ex2.approx.f16x2 %0, %1;" : "=r"(r) : "r"(s));
    return r;
}

#define LDSM4(R, p) do {                                                     \
    uint32_t _ad = (uint32_t)__cvta_generic_to_shared(p);                    \
    asm volatile("ldmatrix.sync.aligned.m8n8.x4.shared.b16 {%0,%1,%2,%3}, [%4];" \
        : "=r"((R)[0]), "=r"((R)[1]), "=r"((R)[2]), "=r"((R)[3]) : "r"(_ad)); \
} while (0)

#define LDSM4T(R, p) do {                                                    \
    uint32_t _ad = (uint32_t)__cvta_generic_to_shared(p);                    \
    asm volatile("ldmatrix.sync.aligned.m8n8.x4.trans.shared.b16 {%0,%1,%2,%3}, [%4];" \
        : "=r"((R)[0]), "=r"((R)[1]), "=r"((R)[2]), "=r"((R)[3]) : "r"(_ad)); \
} while (0)

#define CPA16(dst, src) asm volatile(                                        \
    "cp.async.ca.shared.global [%0], [%1], 16;" ::                           \
    "r"((uint32_t)__cvta_generic_to_shared(dst)), "l"(src))
#define CPA_COMMIT() asm volatile("cp.async.commit_group;")
#define CPA_WAIT1()  asm volatile("cp.async.wait_group 1;")

// ---------------- weight fp32 -> bf16 pre-convert (5 square weights) ----------------
__global__ void k_cvtw(const float* __restrict__ W2, const float* __restrict__ Wq,
                       const float* __restrict__ Wk, const float* __restrict__ Wv,
                       const float* __restrict__ Wo) {
    const float* src[5] = {W2, Wq, Wk, Wv, Wo};
    const int off[5] = {OW2, OWQ, OWK, OWV, OWO};
    int y = blockIdx.y;
    int i = (blockIdx.x*256 + threadIdx.x)*2;
    float2 v = *(const float2*)(src[y] + i);
    *(__nv_bfloat162*)(g_wb + off[y] + i) = __floats2bfloat162_rn(v.x, v.y);
}

// ---------------- Wf = W1 @ Wg (fp32 accum, bf16 store) ----------------
__global__ void k_wfuse(const float* __restrict__ W1, const float* __restrict__ Wg) {
    __shared__ float w1s[128];
    int k = blockIdx.x, t = threadIdx.x;      // 256 threads
    if (t < 128) w1s[t] = W1[k*128 + t];
    __syncthreads();
    float acc = 0.f;
    #pragma unroll 8
    for (int j = 0; j < 128; j++) acc += w1s[j] * Wg[j*256 + t];
    g_wb[OWG + k*256 + t] = __float2bfloat16(acc);
}
// bf = b1 @ Wg + bg
__global__ void k_bfuse(const float* __restrict__ b1, const float* __restrict__ Wg,
                        const float* __restrict__ bg) {
    int t = threadIdx.x;                      // 256 threads, 1 block
    float acc = bg[t];
    #pragma unroll 8
    for (int j = 0; j < 128; j++) acc += b1[j] * Wg[j*256 + t];
    g_bfused[t] = acc;
}

// ---------------- t_params = mish(t_emb) @ Wt + bt ----------------
__global__ void k_tparams(const float* __restrict__ t_emb,
                          const float* __restrict__ Wt,
                          const float* __restrict__ bt) {
    __shared__ float ms[TT];
    int b = blockIdx.x, t = threadIdx.x;
    if (t < TT) {
        float x = t_emb[b*TT + t];
        float sp = (x > 15.f) ? x : log1pf(expf(x));
        ms[t] = x * tanhf(sp);
    }
    __syncthreads();
    float acc = bt[t];
    #pragma unroll 8
    for (int i = 0; i < TT; i++) acc += ms[i] * Wt[i*(2*DD) + t];
    g_tparams[b*2*DD + t] = acc;
}

// ---------------- adj int32 -> bitmask (int4 loads, per-thread word) ----------------
__global__ void k_adjbits(const int* __restrict__ adj) {
    int row = blockIdx.x, t = threadIdx.x;    // 128 threads; thread owns cols 32t..32t+31
    const int4* arow = (const int4*)(adj + (size_t)row*NN);
    unsigned word = 0;
    #pragma unroll
    for (int i = 0; i < 8; i++) {
        int4 v = arow[t*8 + i];
        unsigned nib = (unsigned)(v.x != 0) | ((unsigned)(v.y != 0) << 1)
                     | ((unsigned)(v.z != 0) << 2) | ((unsigned)(v.w != 0) << 3);
        word |= nib << (4*i);
    }
    g_adjbits[(size_t)row*128 + t] = word;
}

// ---------------- layernorm (optional FiLM), vectorized, bf16 out ----------------
__global__ void k_ln(const float* __restrict__ X, const float* __restrict__ tp,
                     const float* __restrict__ gam, const float* __restrict__ bet,
                     __nv_bfloat16* __restrict__ out) {
    int w = threadIdx.x >> 5, lane = threadIdx.x & 31;
    int row = blockIdx.x*4 + w;
    int b = row >> 12;
    int c = 4*lane;
    float4 v = *(const float4*)&X[(size_t)row*DD + c];
    if (tp) {
        float4 s4 = *(const float4*)&tp[b*2*DD + c];
        float4 h4 = *(const float4*)&tp[b*2*DD + DD + c];
        v.x = v.x*(1.f+s4.x)+h4.x; v.y = v.y*(1.f+s4.y)+h4.y;
        v.z = v.z*(1.f+s4.z)+h4.z; v.w = v.w*(1.f+s4.w)+h4.w;
    }
    float s = v.x+v.y+v.z+v.w;
    float ss = v.x*v.x+v.y*v.y+v.z*v.z+v.w*v.w;
    #pragma unroll
    for (int o = 16; o; o >>= 1) {
        s  += __shfl_xor_sync(0xffffffffu, s,  o);
        ss += __shfl_xor_sync(0xffffffffu, ss, o);
    }
    float mu = s*(1.f/128.f);
    float var = ss*(1.f/128.f) - mu*mu;
    float r = rsqrtf(var + 1e-5f);
    float4 gm = *(const float4*)&gam[c];
    float4 bt4 = *(const float4*)&bet[c];
    uint2 o2;
    o2.x = packbf((v.x-mu)*r*gm.x + bt4.x, (v.y-mu)*r*gm.y + bt4.y);
    o2.y = packbf((v.z-mu)*r*gm.z + bt4.z, (v.w-mu)*r*gm.w + bt4.w);
    *(uint2*)&out[(size_t)row*DD + c] = o2;
}

// ---------------- fused GEMM + GLU: h = glu(ln1 @ Wf + bf) ----------------
#define TCP 136
#define GLUP 264
#define GLU_SMEM ((64*TCP + 128*GLUP)*2)
__global__ void __launch_bounds__(256) k_gemm_glu(
        const __nv_bfloat16* __restrict__ A, __nv_bfloat16* __restrict__ out) {
    extern __shared__ __nv_bfloat16 smb[];
    __nv_bfloat16* As = smb;               // [64][136]
    __nv_bfloat16* Ws = smb + 64*TCP;      // [128][264]
    int bm = blockIdx.x*64;
    int t = threadIdx.x;
    {
        const uint4* Ag = (const uint4*)(A + (size_t)bm*128);
        for (int i = t; i < 1024; i += 256) {
            int m = i >> 4, kc = i & 15;
            *(uint4*)(As + m*TCP + kc*8) = Ag[i];
        }
    }
    {
        const __nv_bfloat16* W = g_wb + OWG;
        for (int i = t; i < 4096; i += 256) {
            int k = i >> 5, nc = (i & 31)*8;
            *(uint4*)(Ws + k*GLUP + nc) = *(const uint4*)(W + (size_t)k*256 + nc);
        }
    }
    __syncthreads();

    int w = t >> 5, lane = t & 31;
    int wm = w >> 2, wn = w & 3;          // warp: rows 32*wm, a-cols 32*wn, gate-cols 128+32*wn
    float accA[2][2][2][4], accG[2][2][2][4];
    #pragma unroll
    for (int a = 0; a < 2; a++)
        #pragma unroll
        for (int b = 0; b < 2; b++)
            #pragma unroll
            for (int c = 0; c < 2; c++)
                #pragma unroll
                for (int d = 0; d < 4; d++) { accA[a][b][c][d] = 0.f; accG[a][b][c][d] = 0.f; }

    #pragma unroll
    for (int ks = 0; ks < 8; ks++) {
        unsigned am[2][4];
        #pragma unroll
        for (int mi = 0; mi < 2; mi++) {
            const __nv_bfloat16* p = As
                + (32*wm + 16*mi + (lane&7) + 8*((lane>>3)&1))*TCP
                + 16*ks + 8*(lane>>4);
            LDSM4(am[mi], p);
        }
        #pragma unroll
        for (int ng = 0; ng < 2; ng++) {
            unsigned bwA[4], bwG[4];
            const __nv_bfloat16* pr = Ws + (16*ks + (lane&7) + 8*((lane>>3)&1))*GLUP;
            LDSM4T(bwA, pr + 32*wn + 16*ng + 8*(lane>>4));
            LDSM4T(bwG, pr + 128 + 32*wn + 16*ng + 8*(lane>>4));
            #pragma unroll
            for (int mi = 0; mi < 2; mi++) {
                mma16816(accA[mi][ng][0], am[mi], bwA[0], bwA[1]);
                mma16816(accA[mi][ng][1], am[mi], bwA[2], bwA[3]);
                mma16816(accG[mi][ng][0], am[mi], bwG[0], bwG[1]);
                mma16816(accG[mi][ng][1], am[mi], bwG[2], bwG[3]);
            }
        }
    }

    #pragma unroll
    for (int mi = 0; mi < 2; mi++) {
        int r = bm + 32*wm + 16*mi + (lane>>2);
        #pragma unroll
        for (int ng = 0; ng < 2; ng++) {
            #pragma unroll
            for (int hf = 0; hf < 2; hf++) {
                int j = 32*wn + 16*ng + 8*hf + 2*(lane&3);
                float ba0 = g_bfused[j], ba1 = g_bfused[j+1];
                float bg0 = g_bfused[128+j], bg1 = g_bfused[128+j+1];
                float a00 = accA[mi][ng][hf][0] + ba0;
                float a01 = accA[mi][ng][hf][1] + ba1;
                float a10 = accA[mi][ng][hf][2] + ba0;
                float a11 = accA[mi][ng][hf][3] + ba1;
                float q00 = accG[mi][ng][hf][0] + bg0;
                float q01 = accG[mi][ng][hf][1] + bg1;
                float q10 = accG[mi][ng][hf][2] + bg0;
                float q11 = accG[mi][ng][hf][3] + bg1;
                float h00 = a00 / (1.f + __expf(-q00));
                float h01 = a01 / (1.f + __expf(-q01));
                float h10 = a10 / (1.f + __expf(-q10));
                float h11 = a11 / (1.f + __expf(-q11));
                *(unsigned*)&out[(size_t)r*128 + j]     = packbf(h00, h01);
                *(unsigned*)&out[(size_t)(r+8)*128 + j] = packbf(h10, h11);
            }
        }
    }
}

// ---------------- tensor-core bf16 GEMM: 64-row tiles, bf16 weights ----------------
#define GEMM_TC_SMEM ((64 + 128)*TCP*2)

struct GArgs {
    const __nv_bfloat16* A;
    const __nv_bfloat16* W0; const __nv_bfloat16* W1; const __nv_bfloat16* W2;
    const float* b0; const float* b1; const float* b2;
    const float* res;          // fp32 residual (N==128 only)
    float* outF;               // if set: fp32 out (stride 128)
    void* o0; void* o1; void* o2;
    int N; int multi; int h16; float qs;   // qs applied to by==0 h16 output
};

__global__ void __launch_bounds__(256) k_gemm_tc(GArgs g) {
    extern __shared__ __nv_bfloat16 smb[];
    __nv_bfloat16* As = smb;               // [64][TCP]
    __nv_bfloat16* Ws = smb + 64*TCP;      // [128][TCP]
    int by = blockIdx.y;
    const __nv_bfloat16* W; const float* bias; void* outB; int bn;
    if (g.multi) {
        W    = by==0 ? g.W0 : by==1 ? g.W1 : g.W2;
        bias = by==0 ? g.b0 : by==1 ? g.b1 : g.b2;
        outB = by==0 ? g.o0 : by==1 ? g.o1 : g.o2;
        bn = 0;
    } else { W = g.W0; bias = g.b0; outB = g.o0; bn = by*128; }
    float osc = (g.multi && by==0) ? g.qs : 1.f;
    int bm = blockIdx.x*64;
    int t = threadIdx.x;

    {
        const uint4* Ag = (const uint4*)(g.A + (size_t)bm*128);
        for (int i = t; i < 1024; i += 256) {
            int m = i >> 4, kc = i & 15;
            *(uint4*)(As + m*TCP + kc*8) = Ag[i];
        }
    }
    for (int i = t; i < 2048; i += 256) {
        int k = i >> 4, nc = (i & 15)*8;
        *(uint4*)(Ws + k*TCP + nc) = *(const uint4*)(W + (size_t)k*g.N + bn + nc);
    }
    __syncthreads();

    int w = t >> 5, lane = t & 31;
    int wm = w >> 2, wn = w & 3;
    float acc[2][2][2][4];
    #pragma unroll
    for (int a = 0; a < 2; a++)
        #pragma unroll
        for (int b = 0; b < 2; b++)
            #pragma unroll
            for (int c = 0; c < 2; c++)
                #pragma unroll
                for (int d = 0; d < 4; d++) acc[a][b][c][d] = 0.f;

    #pragma unroll
    for (int ks = 0; ks < 8; ks++) {
        unsigned am[2][4];
        #pragma unroll
        for (int mi = 0; mi < 2; mi++) {
            const __nv_bfloat16* p = As
                + (32*wm + 16*mi + (lane&7) + 8*((lane>>3)&1))*TCP
                + 16*ks + 8*(lane>>4);
            LDSM4(am[mi], p);
        }
        #pragma unroll
        for (int ng = 0; ng < 2; ng++) {
            unsigned bw[4];
            const __nv_bfloat16* p = Ws
                + (16*ks + (lane&7) + 8*((lane>>3)&1))*TCP
                + 32*wn + 16*ng + 8*(lane>>4);
            LDSM4T(bw, p);
            #pragma unroll
            for (int mi = 0; mi < 2; mi++) {
                mma16816(acc[mi][ng][0], am[mi], bw[0], bw[1]);
                mma16816(acc[mi][ng][1], am[mi], bw[2], bw[3]);
            }
        }
    }

    int ost = g.multi ? 128 : g.N;
    #pragma unroll
    for (int mi = 0; mi < 2; mi++) {
        int r = bm + 32*wm + 16*mi + (lane>>2);
        #pragma unroll
        for (int ng = 0; ng < 2; ng++) {
            #pragma unroll
            for (int hf = 0; hf < 2; hf++) {
                int c = bn + 32*wn + 16*ng + 8*hf + 2*(lane&3);
                float bx = bias[c], byv = bias[c+1];
                float v00 = acc[mi][ng][hf][0] + bx;
                float v01 = acc[mi][ng][hf][1] + byv;
                float v10 = acc[mi][ng][hf][2] + bx;
                float v11 = acc[mi][ng][hf][3] + byv;
                if (g.outF) {
                    if (g.res) {
                        v00 += g.res[(size_t)r*128 + c];
                        v01 += g.res[(size_t)r*128 + c + 1];
                        v10 += g.res[(size_t)(r+8)*128 + c];
                        v11 += g.res[(size_t)(r+8)*128 + c + 1];
                    }
                    *(float2*)&g.outF[(size_t)r*ost + c]     = make_float2(v00, v01);
                    *(float2*)&g.outF[(size_t)(r+8)*ost + c] = make_float2(v10, v11);
                } else if (g.h16) {
                    __half* ob = (__half*)outB;
                    *(unsigned*)&ob[(size_t)r*ost + c]     = packh(v00*osc, v01*osc);
                    *(unsigned*)&ob[(size_t)(r+8)*ost + c] = packh(v10*osc, v11*osc);
                } else {
                    __nv_bfloat16* ob = (__nv_bfloat16*)outB;
                    *(unsigned*)&ob[(size_t)r*ost + c]     = packbf(v00, v01);
                    *(unsigned*)&ob[(size_t)(r+8)*ost + c] = packbf(v10, v11);
                }
            }
        }
    }
}

// ---------------- flash attention: f16 QK-acc, packed exp, cp.async, reg masks ----------------
#define KVP 56
#define ATTN_SMEM ((128*KVP + 4*64*KVP)*2)
__global__ void __launch_bounds__(256) k_attn(
        const __half* __restrict__ Q, const __half* __restrict__ K,
        const __half* __restrict__ V, __nv_bfloat16* __restrict__ O) {
    extern __shared__ __half smh[];
    __half* Qs = smh;                                   // [128][56]
    __half* KV0 = smh + 128*KVP;
    __half* KV1 = KV0 + 2*64*KVP;

    int i0 = blockIdx.x*128, h = blockIdx.y, b = blockIdx.z;
    int t = threadIdx.x, w = t >> 5, lane = t & 31;

    {
        const __half* qb = Q + ((size_t)(b*NN + i0))*DD + h*HDIM;
        for (int i = t; i < 512; i += 256) {
            int r = i >> 2, c = (i & 3)*8;
            *(uint4*)(Qs + r*KVP + c) = *(const uint4*)(qb + (size_t)r*DD + c);
        }
    }
    {
        int r = t >> 2, c = (t & 3)*8;
        const __half* kb = K + ((size_t)(b*NN + r))*DD + h*HDIM + c;
        const __half* vb = V + ((size_t)(b*NN + r))*DD + h*HDIM + c;
        CPA16(KV0 + r*KVP + c, kb);
        CPA16(KV0 + 64*KVP + r*KVP + c, vb);
    }
    CPA_COMMIT();
    __syncthreads();

    unsigned qa[2][4];
    #pragma unroll
    for (int s = 0; s < 2; s++) {
        const __half* p = Qs + (16*w + (lane&7) + 8*((lane>>3)&1))*KVP
                          + 16*s + 8*(lane>>4);
        LDSM4(qa[s], p);
    }

    float l0 = 0.f, l1 = 0.f;
    float o[4][4];
    #pragma unroll
    for (int i = 0; i < 4; i++)
        #pragma unroll
        for (int j = 0; j < 4; j++) o[i][j] = 0.f;

    int r0 = 16*w + (lane>>2), r1 = r0 + 8;
    const unsigned* mg0 = g_adjbits + (size_t)(i0 + r0)*(NN/32);
    const unsigned* mg1 = g_adjbits + (size_t)(i0 + r1)*(NN/32);
    uint2 mk0 = *(const uint2*)mg0;
    uint2 mk1 = *(const uint2*)mg1;

    for (int jt = 0; jt < NN/64; jt++) {
        __half* cur = (jt & 1) ? KV1 : KV0;
        __half* nxt = (jt & 1) ? KV0 : KV1;
        if (jt < NN/64 - 1) {
            int j0n = (jt+1)*64;
            int r = t >> 2, c = (t & 3)*8;
            const __half* kb = K + ((size_t)(b*NN + j0n + r))*DD + h*HDIM + c;
            const __half* vb = V + ((size_t)(b*NN + j0n + r))*DD + h*HDIM + c;
            CPA16(nxt + r*KVP + c, kb);
            CPA16(nxt + 64*KVP + r*KVP + c, vb);
        }
        CPA_COMMIT();
        uint2 nmk0 = mk0, nmk1 = mk1;
        if (jt < NN/64 - 1) {
            nmk0 = *(const uint2*)(mg0 + 2*(jt+1));
            nmk1 = *(const uint2*)(mg1 + 2*(jt+1));
        }
        CPA_WAIT1();
        __syncthreads();

        __half* Ks = cur;
        __half* Vs = cur + 64*KVP;

        // S = Q K^T with f16 accumulators (Q pre-scaled by SCALE*log2e)
        unsigned sc2[8][2];
        #pragma unroll
        for (int nf = 0; nf < 8; nf++) {
            unsigned kb4[4];
            const __half* p = Ks + (8*nf + (lane&7))*KVP + 8*(lane>>3);
            LDSM4(kb4, p);
            sc2[nf][0] = 0u; sc2[nf][1] = 0u;
            mma16816hh(sc2[nf], qa[0], kb4[0], kb4[1]);
            mma16816hh(sc2[nf], qa[1], kb4[2], kb4[3]);
        }

        // mask (additive -inf, packed) + exp2 (f16x2 MUFU); results are PV A-frags
        unsigned pex[8][2];
        __half2 la = __floats2half2_rn(0.f, 0.f), lb = la;
        #pragma unroll
        for (int nf = 0; nf < 8; nf++) {
            int sh = (8*nf + 2*(lane&3)) & 31;
            unsigned ua = (nf < 4) ? mk0.x : mk0.y;
            unsigned ub = (nf < 4) ? mk1.x : mk1.y;
            unsigned na = ~ua, nb = ~ub;
            unsigned m0 = ((na>>sh)&1u)*0xFC00u | ((na>>(sh+1))&1u)*0xFC000000u;
            unsigned m1 = ((nb>>sh)&1u)*0xFC00u | ((nb>>(sh+1))&1u)*0xFC000000u;
            __half2 s0 = __hadd2(*(__half2*)&sc2[nf][0], *(__half2*)&m0);
            __half2 s1 = __hadd2(*(__half2*)&sc2[nf][1], *(__half2*)&m1);
            unsigned e0 = ex2p(*(unsigned*)&s0);
            unsigned e1 = ex2p(*(unsigned*)&s1);
            pex[nf][0] = e0; pex[nf][1] = e1;
            la = __hadd2(la, *(__half2*)&e0);
            lb = __hadd2(lb, *(__half2*)&e1);
        }
        float2 fa = __half22float2(la), fb = __half22float2(lb);
        l0 += fa.x + fa.y;
        l1 += fb.x + fb.y;

        // O += P V (f32 accum)
        #pragma unroll
        for (int ks = 0; ks < 4; ks++) {
            unsigned pa[4] = { pex[2*ks][0], pex[2*ks][1],
                               pex[2*ks+1][0], pex[2*ks+1][1] };
            #pragma unroll
            for (int np = 0; np < 2; np++) {
                unsigned vb4[4];
                const __half* p = Vs
                    + (16*ks + (lane&7) + 8*((lane>>3)&1))*KVP
                    + 16*np + 8*(lane>>4);
                LDSM4T(vb4, p);
                mma16816h(o[2*np],     pa, vb4[0], vb4[1]);
                mma16816h(o[2*np + 1], pa, vb4[2], vb4[3]);
            }
        }
        __syncthreads();
        mk0 = nmk0; mk1 = nmk1;
    }

    l0 += __shfl_xor_sync(0xffffffffu, l0, 1);
    l0 += __shfl_xor_sync(0xffffffffu, l0, 2);
    l1 += __shfl_xor_sync(0xffffffffu, l1, 1);
    l1 += __shfl_xor_sync(0xffffffffu, l1, 2);
    float inv0 = 1.f / l0, inv1 = 1.f / l1;
    int gi0 = i0 + r0, gi1 = i0 + r1;
    #pragma unroll
    for (int nd = 0; nd < 4; nd++) {
        int col = h*HDIM + 8*nd + 2*(lane&3);
        *(unsigned*)&O[((size_t)(b*NN) + gi0)*DD + col] = packbf(o[nd][0]*inv0, o[nd][1]*inv0);
        *(unsigned*)&O[((size_t)(b*NN) + gi1)*DD + col] = packbf(o[nd][2]*inv1, o[nd][3]*inv1);
    }
}

// ---------------- launch ----------------
extern "C" void kernel_launch(void* const* d_in, const int* in_sizes, int n_in,
                              void* d_out, int out_size) {
    const float* x     = (const float*)d_in[0];
    const float* t_emb = (const float*)d_in[1];
    const int*   adj   = (const int*)  d_in[2];
    const float* Wt  = (const float*)d_in[3];
    const float* bt  = (const float*)d_in[4];
    const float* W1  = (const float*)d_in[5];
    const float* b1  = (const float*)d_in[6];
    const float* Wg  = (const float*)d_in[7];
    const float* bg  = (const float*)d_in[8];
    const float* W2  = (const float*)d_in[9];
    const float* b2  = (const float*)d_in[10];
    const float* Wq  = (const float*)d_in[11];
    const float* bq  = (const float*)d_in[12];
    const float* Wk  = (const float*)d_in[13];
    const float* bk  = (const float*)d_in[14];
    const float* Wv  = (const float*)d_in[15];
    const float* bv  = (const float*)d_in[16];
    const float* Wo  = (const float*)d_in[17];
    const float* bo  = (const float*)d_in[18];
    const float* g1  = (const float*)d_in[19];
    const float* be1 = (const float*)d_in[20];
    const float* g2  = (const float*)d_in[21];
    const float* be2 = (const float*)d_in[22];
    float* out = (float*)d_out;

    float *pTP, *pX2;
    __nv_bfloat16 *pb1, *pb2, *pWB;
    __half *pq, *pk, *pv;
    cudaGetSymbolAddress((void**)&pTP, g_tparams);
    cudaGetSymbolAddress((void**)&pX2, g_x2);
    cudaGetSymbolAddress((void**)&pb1, g_bf1);
    cudaGetSymbolAddress((void**)&pb2, g_bf2);
    cudaGetSymbolAddress((void**)&pWB, g_wb);
    cudaGetSymbolAddress((void**)&pq,  g_q);
    cudaGetSymbolAddress((void**)&pk,  g_k);
    cudaGetSymbolAddress((void**)&pv,  g_v);

    cudaFuncSetAttribute(k_gemm_tc,  cudaFuncAttributeMaxDynamicSharedMemorySize, GEMM_TC_SMEM);
    cudaFuncSetAttribute(k_gemm_glu, cudaFuncAttributeMaxDynamicSharedMemorySize, GLU_SMEM);
    cudaFuncSetAttribute(k_attn,     cudaFuncAttributeMaxDynamicSharedMemorySize, ATTN_SMEM);

    k_cvtw<<<dim3(32,5), 256>>>(W2, Wq, Wk, Wv, Wo);
    k_wfuse<<<128, 256>>>(W1, Wg);
    k_bfuse<<<1, 256>>>(b1, Wg, bg);
    k_tparams<<<BB, 256>>>(t_emb, Wt, bt);
    k_adjbits<<<NN, 128>>>(adj);
    // ln1 with FiLM -> bf16 (pb1)
    k_ln<<<M_ROWS/4, 128>>>(x, pTP, g1, be1, pb1);
    // h = glu(ln1 @ Wf + bf) -> bf16 (pb2)   [fuses W1, Wg, GLU]
    k_gemm_glu<<<256, 256, GLU_SMEM>>>(pb1, pb2);

    GArgs a;
    // x2 = x + h @ W2 + b2 -> fp32 (pX2)
    a = {pb2, pWB+OW2,0,0, b2,0,0, x, pX2, 0,0,0, 128, 0, 0, 1.f};
    k_gemm_tc<<<dim3(256,1), 256, GEMM_TC_SMEM>>>(a);
    // ln2 -> bf16 (pb1)
    k_ln<<<M_ROWS/4, 128>>>(pX2, nullptr, g2, be2, pb1);
    // q,k,v fused (grid.y = 3), f16 out; q pre-scaled by SCALE*log2e
    a = {pb1, pWB+OWQ,pWB+OWK,pWB+OWV, bq,bk,bv, 0, 0, pq,pk,pv, 128, 1, 1, EXC};
    k_gemm_tc<<<dim3(256,3), 256, GEMM_TC_SMEM>>>(a);
    // masked flash attention -> bf16 (pb1)
    k_attn<<<dim3(NN/128, HH, BB), 256, ATTN_SMEM>>>(pq, pk, pv, pb1);
    // out = x2 + attn @ Wo + bo -> fp32 d_out
    a = {pb1, pWB+OWO,0,0, bo,0,0, pX2, out, 0,0,0, 128, 0, 0, 1.f};
    k_gemm_tc<<<dim3(256,1), 256, GEMM_TC_SMEM>>>(a);
}

// round 7
// speedup vs baseline: 1.0828x; 1.0828x over previous
#include <cuda_runtime.h>
#include <cuda_bf16.h>
#include <cuda_fp16.h>
#include <cstdint>

#define BB 4
#define NN 4096
#define DD 128
#define TT 128
#define HH 4
#define HDIM 32
#define M_ROWS (BB*NN)          // 16384
#define SCALE 0.17677669529663687f
#define EXC (SCALE * 1.4426950408889634f)   // scale * log2(e), folded into Q

// ---------------- scratch ----------------
__device__ float          g_tparams[BB*2*DD];
__device__ float          g_bfused[2*DD];             // fused bias b1@Wg+bg
__device__ float          g_x2[M_ROWS*DD];            // fp32 residual
__device__ __nv_bfloat16  g_bf1[M_ROWS*DD];
__device__ __nv_bfloat16  g_bf2[M_ROWS*DD];
__device__ __half         g_q[M_ROWS*DD];
__device__ __half         g_k[M_ROWS*DD];
__device__ __half         g_v[M_ROWS*DD];
__device__ unsigned       g_adjbits[NN*(NN/32)];      // 2 MB bitmask
__device__ __nv_bfloat16  g_wb[131072];               // pre-converted weights

// weight offsets in g_wb
#define OWG 0          // fused W1@Wg  [128][256]
#define OW2 32768
#define OWQ 49152
#define OWK 65536
#define OWV 81920
#define OWO 98304

// ---------------- helpers ----------------
__device__ __forceinline__ unsigned packbf(float x, float y) {
    __nv_bfloat162 h = __floats2bfloat162_rn(x, y);
    return *reinterpret_cast<unsigned*>(&h);
}
__device__ __forceinline__ unsigned packh(float x, float y) {
    __half2 h = __floats2half2_rn(x, y);
    return *reinterpret_cast<unsigned*>(&h);
}

__device__ __forceinline__ void mma16816(float* c, const unsigned* a, unsigned b0, unsigned b1) {
    asm volatile(
        "mma.sync.aligned.m16n8k16.row.col.f32.bf16.bf16.f32 "
        "{%0,%1,%2,%3}, {%4,%5,%6,%7}, {%8,%9}, {%0,%1,%2,%3};"
        : "+f"(c[0]), "+f"(c[1]), "+f"(c[2]), "+f"(c[3])
        : "r"(a[0]), "r"(a[1]), "r"(a[2]), "r"(a[3]), "r"(b0), "r"(b1));
}
// f16-accumulator mma: D = 2 regs of f16x2
__device__ __forceinline__ void mma16816hh(unsigned* c, const unsigned* a, unsigned b0, unsigned b1) {
    asm volatile(
        "mma.sync.aligned.m16n8k16.row.col.f16.f16.f16.f16 "
        "{%0,%1}, {%2,%3,%4,%5}, {%6,%7}, {%0,%1};"
        : "+r"(c[0]), "+r"(c[1])
        : "r"(a[0]), "r"(a[1]), "r"(a[2]), "r"(a[3]), "r"(b0), "r"(b1));
}
__device__ __forceinline__ unsigned ex2p(unsigned s) {
    unsigned r;
    asm("ex2.approx.f16x2 %0, %1;" : "=r"(r) : "r"(s));
    return r;
}

#define LDSM4(R, p) do {                                                     \
    uint32_t _ad = (uint32_t)__cvta_generic_to_shared(p);                    \
    asm volatile("ldmatrix.sync.aligned.m8n8.x4.shared.b16 {%0,%1,%2,%3}, [%4];" \
        : "=r"((R)[0]), "=r"((R)[1]), "=r"((R)[2]), "=r"((R)[3]) : "r"(_ad)); \
} while (0)

#define LDSM4T(R, p) do {                                                    \
    uint32_t _ad = (uint32_t)__cvta_generic_to_shared(p);                    \
    asm volatile("ldmatrix.sync.aligned.m8n8.x4.trans.shared.b16 {%0,%1,%2,%3}, [%4];" \
        : "=r"((R)[0]), "=r"((R)[1]), "=r"((R)[2]), "=r"((R)[3]) : "r"(_ad)); \
} while (0)

#define CPA16(dst, src) asm volatile(                                        \
    "cp.async.ca.shared.global [%0], [%1], 16;" ::                           \
    "r"((uint32_t)__cvta_generic_to_shared(dst)), "l"(src))
#define CPA_COMMIT() asm volatile("cp.async.commit_group;")
#define CPA_WAIT1()  asm volatile("cp.async.wait_group 1;")

// ---------------- fused pre-pass: cvtw + wfuse + bfuse + tparams + adjbits ----------------
// grid layout (256 threads each):
//   [0,160)      : cvtw   (5 weights x 32 blocks)
//   [160,288)    : wfuse  (128 blocks, one k-row each)
//   288          : bfuse
//   [289,305)    : tparams (16 blocks: 4 batches x 4 col-quarters, 4 thr/col)
//   [305,2353)   : adjbits (2048 blocks, 2 rows each)
__global__ void __launch_bounds__(256) k_prep(
        const float* __restrict__ W1, const float* __restrict__ Wg,
        const float* __restrict__ b1, const float* __restrict__ bg,
        const float* __restrict__ W2, const float* __restrict__ Wq,
        const float* __restrict__ Wk, const float* __restrict__ Wv,
        const float* __restrict__ Wo,
        const float* __restrict__ t_emb, const float* __restrict__ Wt,
        const float* __restrict__ bt, const int* __restrict__ adj) {
    int bx = blockIdx.x, t = threadIdx.x;
    if (bx < 160) {                         // ---- cvtw
        const float* src[5] = {W2, Wq, Wk, Wv, Wo};
        const int off[5] = {OW2, OWQ, OWK, OWV, OWO};
        int y = bx >> 5;
        int i = (((bx & 31)*256) + t)*2;
        float2 v = *(const float2*)(src[y] + i);
        *(__nv_bfloat162*)(g_wb + off[y] + i) = __floats2bfloat162_rn(v.x, v.y);
    } else if (bx < 288) {                  // ---- wfuse: Wf[k][:] = W1[k][:] @ Wg
        __shared__ float w1s[128];
        int k = bx - 160;
        if (t < 128) w1s[t] = W1[k*128 + t];
        __syncthreads();
        float acc = 0.f;
        #pragma unroll 8
        for (int j = 0; j < 128; j++) acc += w1s[j] * Wg[j*256 + t];
        g_wb[OWG + k*256 + t] = __float2bfloat16(acc);
    } else if (bx == 288) {                 // ---- bfuse
        float acc = bg[t];
        #pragma unroll 8
        for (int j = 0; j < 128; j++) acc += b1[j] * Wg[j*256 + t];
        g_bfused[t] = acc;
    } else if (bx < 305) {                  // ---- tparams (4 thr/col)
        __shared__ float ms[TT];
        int id = bx - 289;
        int b = id >> 2, q = id & 3;
        if (t < TT) {
            float x = t_emb[b*TT + t];
            float sp = (x > 15.f) ? x : log1pf(expf(x));
            ms[t] = x * tanhf(sp);
        }
        __syncthreads();
        int col = q*64 + (t >> 2);
        int sub = t & 3;
        float acc = 0.f;
        #pragma unroll 8
        for (int i = sub*32; i < sub*32 + 32; i++) acc += ms[i] * Wt[i*(2*DD) + col];
        acc += __shfl_xor_sync(0xffffffffu, acc, 1);
        acc += __shfl_xor_sync(0xffffffffu, acc, 2);
        if (sub == 0) g_tparams[b*2*DD + col] = acc + bt[col];
    } else {                                // ---- adjbits (2 rows/block)
        int idx = bx - 305;
        int row = idx*2 + (t >> 7);
        int wi = t & 127;
        const int4* arow = (const int4*)(adj + (size_t)row*NN);
        unsigned word = 0;
        #pragma unroll
        for (int i = 0; i < 8; i++) {
            int4 v = arow[wi*8 + i];
            unsigned nib = (unsigned)(v.x != 0) | ((unsigned)(v.y != 0) << 1)
                         | ((unsigned)(v.z != 0) << 2) | ((unsigned)(v.w != 0) << 3);
            word |= nib << (4*i);
        }
        g_adjbits[(size_t)row*128 + wi] = word;
    }
}

// ---------------- layernorm (optional FiLM), vectorized, bf16 out ----------------
__global__ void k_ln(const float* __restrict__ X, const float* __restrict__ tp,
                     const float* __restrict__ gam, const float* __restrict__ bet,
                     __nv_bfloat16* __restrict__ out) {
    int w = threadIdx.x >> 5, lane = threadIdx.x & 31;
    int row = blockIdx.x*4 + w;
    int b = row >> 12;
    int c = 4*lane;
    float4 v = *(const float4*)&X[(size_t)row*DD + c];
    if (tp) {
        float4 s4 = *(const float4*)&tp[b*2*DD + c];
        float4 h4 = *(const float4*)&tp[b*2*DD + DD + c];
        v.x = v.x*(1.f+s4.x)+h4.x; v.y = v.y*(1.f+s4.y)+h4.y;
        v.z = v.z*(1.f+s4.z)+h4.z; v.w = v.w*(1.f+s4.w)+h4.w;
    }
    float s = v.x+v.y+v.z+v.w;
    float ss = v.x*v.x+v.y*v.y+v.z*v.z+v.w*v.w;
    #pragma unroll
    for (int o = 16; o; o >>= 1) {
        s  += __shfl_xor_sync(0xffffffffu, s,  o);
        ss += __shfl_xor_sync(0xffffffffu, ss, o);
    }
    float mu = s*(1.f/128.f);
    float var = ss*(1.f/128.f) - mu*mu;
    float r = rsqrtf(var + 1e-5f);
    float4 gm = *(const float4*)&gam[c];
    float4 bt4 = *(const float4*)&bet[c];
    uint2 o2;
    o2.x = packbf((v.x-mu)*r*gm.x + bt4.x, (v.y-mu)*r*gm.y + bt4.y);
    o2.y = packbf((v.z-mu)*r*gm.z + bt4.z, (v.w-mu)*r*gm.w + bt4.w);
    *(uint2*)&out[(size_t)row*DD + c] = o2;
}

// ---------------- fused GEMM + GLU: h = glu(ln1 @ Wf + bf) ----------------
#define TCP 136
#define GLUP 264
#define GLU_SMEM ((64*TCP + 128*GLUP)*2)
__global__ void __launch_bounds__(256) k_gemm_glu(
        const __nv_bfloat16* __restrict__ A, __nv_bfloat16* __restrict__ out) {
    extern __shared__ __nv_bfloat16 smb[];
    __nv_bfloat16* As = smb;               // [64][136]
    __nv_bfloat16* Ws = smb + 64*TCP;      // [128][264]
    int bm = blockIdx.x*64;
    int t = threadIdx.x;
    {
        const uint4* Ag = (const uint4*)(A + (size_t)bm*128);
        for (int i = t; i < 1024; i += 256) {
            int m = i >> 4, kc = i & 15;
            *(uint4*)(As + m*TCP + kc*8) = Ag[i];
        }
    }
    {
        const __nv_bfloat16* W = g_wb + OWG;
        for (int i = t; i < 4096; i += 256) {
            int k = i >> 5, nc = (i & 31)*8;
            *(uint4*)(Ws + k*GLUP + nc) = *(const uint4*)(W + (size_t)k*256 + nc);
        }
    }
    __syncthreads();

    int w = t >> 5, lane = t & 31;
    int wm = w >> 2, wn = w & 3;
    float accA[2][2][2][4], accG[2][2][2][4];
    #pragma unroll
    for (int a = 0; a < 2; a++)
        #pragma unroll
        for (int b = 0; b < 2; b++)
            #pragma unroll
            for (int c = 0; c < 2; c++)
                #pragma unroll
                for (int d = 0; d < 4; d++) { accA[a][b][c][d] = 0.f; accG[a][b][c][d] = 0.f; }

    #pragma unroll
    for (int ks = 0; ks < 8; ks++) {
        unsigned am[2][4];
        #pragma unroll
        for (int mi = 0; mi < 2; mi++) {
            const __nv_bfloat16* p = As
                + (32*wm + 16*mi + (lane&7) + 8*((lane>>3)&1))*TCP
                + 16*ks + 8*(lane>>4);
            LDSM4(am[mi], p);
        }
        #pragma unroll
        for (int ng = 0; ng < 2; ng++) {
            unsigned bwA[4], bwG[4];
            const __nv_bfloat16* pr = Ws + (16*ks + (lane&7) + 8*((lane>>3)&1))*GLUP;
            LDSM4T(bwA, pr + 32*wn + 16*ng + 8*(lane>>4));
            LDSM4T(bwG, pr + 128 + 32*wn + 16*ng + 8*(lane>>4));
            #pragma unroll
            for (int mi = 0; mi < 2; mi++) {
                mma16816(accA[mi][ng][0], am[mi], bwA[0], bwA[1]);
                mma16816(accA[mi][ng][1], am[mi], bwA[2], bwA[3]);
                mma16816(accG[mi][ng][0], am[mi], bwG[0], bwG[1]);
                mma16816(accG[mi][ng][1], am[mi], bwG[2], bwG[3]);
            }
        }
    }

    #pragma unroll
    for (int mi = 0; mi < 2; mi++) {
        int r = bm + 32*wm + 16*mi + (lane>>2);
        #pragma unroll
        for (int ng = 0; ng < 2; ng++) {
            #pragma unroll
            for (int hf = 0; hf < 2; hf++) {
                int j = 32*wn + 16*ng + 8*hf + 2*(lane&3);
                float ba0 = g_bfused[j], ba1 = g_bfused[j+1];
                float bg0 = g_bfused[128+j], bg1 = g_bfused[128+j+1];
                float a00 = accA[mi][ng][hf][0] + ba0;
                float a01 = accA[mi][ng][hf][1] + ba1;
                float a10 = accA[mi][ng][hf][2] + ba0;
                float a11 = accA[mi][ng][hf][3] + ba1;
                float q00 = accG[mi][ng][hf][0] + bg0;
                float q01 = accG[mi][ng][hf][1] + bg1;
                float q10 = accG[mi][ng][hf][2] + bg0;
                float q11 = accG[mi][ng][hf][3] + bg1;
                float h00 = a00 / (1.f + __expf(-q00));
                float h01 = a01 / (1.f + __expf(-q01));
                float h10 = a10 / (1.f + __expf(-q10));
                float h11 = a11 / (1.f + __expf(-q11));
                *(unsigned*)&out[(size_t)r*128 + j]     = packbf(h00, h01);
                *(unsigned*)&out[(size_t)(r+8)*128 + j] = packbf(h10, h11);
            }
        }
    }
}

// ---------------- tensor-core bf16 GEMM: 64-row tiles, bf16 weights ----------------
#define GEMM_TC_SMEM ((64 + 128)*TCP*2)

struct GArgs {
    const __nv_bfloat16* A;
    const __nv_bfloat16* W0; const __nv_bfloat16* W1; const __nv_bfloat16* W2;
    const float* b0; const float* b1; const float* b2;
    const float* res;
    float* outF;
    void* o0; void* o1; void* o2;
    int N; int multi; int h16; float qs;
};

__global__ void __launch_bounds__(256) k_gemm_tc(GArgs g) {
    extern __shared__ __nv_bfloat16 smb[];
    __nv_bfloat16* As = smb;               // [64][TCP]
    __nv_bfloat16* Ws = smb + 64*TCP;      // [128][TCP]
    int by = blockIdx.y;
    const __nv_bfloat16* W; const float* bias; void* outB; int bn;
    if (g.multi) {
        W    = by==0 ? g.W0 : by==1 ? g.W1 : g.W2;
        bias = by==0 ? g.b0 : by==1 ? g.b1 : g.b2;
        outB = by==0 ? g.o0 : by==1 ? g.o1 : g.o2;
        bn = 0;
    } else { W = g.W0; bias = g.b0; outB = g.o0; bn = by*128; }
    float osc = (g.multi && by==0) ? g.qs : 1.f;
    int bm = blockIdx.x*64;
    int t = threadIdx.x;

    {
        const uint4* Ag = (const uint4*)(g.A + (size_t)bm*128);
        for (int i = t; i < 1024; i += 256) {
            int m = i >> 4, kc = i & 15;
            *(uint4*)(As + m*TCP + kc*8) = Ag[i];
        }
    }
    for (int i = t; i < 2048; i += 256) {
        int k = i >> 4, nc = (i & 15)*8;
        *(uint4*)(Ws + k*TCP + nc) = *(const uint4*)(W + (size_t)k*g.N + bn + nc);
    }
    __syncthreads();

    int w = t >> 5, lane = t & 31;
    int wm = w >> 2, wn = w & 3;
    float acc[2][2][2][4];
    #pragma unroll
    for (int a = 0; a < 2; a++)
        #pragma unroll
        for (int b = 0; b < 2; b++)
            #pragma unroll
            for (int c = 0; c < 2; c++)
                #pragma unroll
                for (int d = 0; d < 4; d++) acc[a][b][c][d] = 0.f;

    #pragma unroll
    for (int ks = 0; ks < 8; ks++) {
        unsigned am[2][4];
        #pragma unroll
        for (int mi = 0; mi < 2; mi++) {
            const __nv_bfloat16* p = As
                + (32*wm + 16*mi + (lane&7) + 8*((lane>>3)&1))*TCP
                + 16*ks + 8*(lane>>4);
            LDSM4(am[mi], p);
        }
        #pragma unroll
        for (int ng = 0; ng < 2; ng++) {
            unsigned bw[4];
            const __nv_bfloat16* p = Ws
                + (16*ks + (lane&7) + 8*((lane>>3)&1))*TCP
                + 32*wn + 16*ng + 8*(lane>>4);
            LDSM4T(bw, p);
            #pragma unroll
            for (int mi = 0; mi < 2; mi++) {
                mma16816(acc[mi][ng][0], am[mi], bw[0], bw[1]);
                mma16816(acc[mi][ng][1], am[mi], bw[2], bw[3]);
            }
        }
    }

    int ost = g.multi ? 128 : g.N;
    #pragma unroll
    for (int mi = 0; mi < 2; mi++) {
        int r = bm + 32*wm + 16*mi + (lane>>2);
        #pragma unroll
        for (int ng = 0; ng < 2; ng++) {
            #pragma unroll
            for (int hf = 0; hf < 2; hf++) {
                int c = bn + 32*wn + 16*ng + 8*hf + 2*(lane&3);
                float bx = bias[c], byv = bias[c+1];
                float v00 = acc[mi][ng][hf][0] + bx;
                float v01 = acc[mi][ng][hf][1] + byv;
                float v10 = acc[mi][ng][hf][2] + bx;
                float v11 = acc[mi][ng][hf][3] + byv;
                if (g.outF) {
                    if (g.res) {
                        v00 += g.res[(size_t)r*128 + c];
                        v01 += g.res[(size_t)r*128 + c + 1];
                        v10 += g.res[(size_t)(r+8)*128 + c];
                        v11 += g.res[(size_t)(r+8)*128 + c + 1];
                    }
                    *(float2*)&g.outF[(size_t)r*ost + c]     = make_float2(v00, v01);
                    *(float2*)&g.outF[(size_t)(r+8)*ost + c] = make_float2(v10, v11);
                } else if (g.h16) {
                    __half* ob = (__half*)outB;
                    *(unsigned*)&ob[(size_t)r*ost + c]     = packh(v00*osc, v01*osc);
                    *(unsigned*)&ob[(size_t)(r+8)*ost + c] = packh(v10*osc, v11*osc);
                } else {
                    __nv_bfloat16* ob = (__nv_bfloat16*)outB;
                    *(unsigned*)&ob[(size_t)r*ost + c]     = packbf(v00, v01);
                    *(unsigned*)&ob[(size_t)(r+8)*ost + c] = packbf(v10, v11);
                }
            }
        }
    }
}

// ---------------- flash attention: all-f16 mma, packed exp, cp.async, reg masks ----------------
#define KVP 56
#define ATTN_SMEM ((128*KVP + 4*64*KVP)*2)
__global__ void __launch_bounds__(256) k_attn(
        const __half* __restrict__ Q, const __half* __restrict__ K,
        const __half* __restrict__ V, __nv_bfloat16* __restrict__ O) {
    extern __shared__ __half smh[];
    __half* Qs = smh;                                   // [128][56]
    __half* KV0 = smh + 128*KVP;
    __half* KV1 = KV0 + 2*64*KVP;

    int i0 = blockIdx.x*128, h = blockIdx.y, b = blockIdx.z;
    int t = threadIdx.x, w = t >> 5, lane = t & 31;

    {
        const __half* qb = Q + ((size_t)(b*NN + i0))*DD + h*HDIM;
        for (int i = t; i < 512; i += 256) {
            int r = i >> 2, c = (i & 3)*8;
            *(uint4*)(Qs + r*KVP + c) = *(const uint4*)(qb + (size_t)r*DD + c);
        }
    }
    {
        int r = t >> 2, c = (t & 3)*8;
        const __half* kb = K + ((size_t)(b*NN + r))*DD + h*HDIM + c;
        const __half* vb = V + ((size_t)(b*NN + r))*DD + h*HDIM + c;
        CPA16(KV0 + r*KVP + c, kb);
        CPA16(KV0 + 64*KVP + r*KVP + c, vb);
    }
    CPA_COMMIT();
    __syncthreads();

    unsigned qa[2][4];
    #pragma unroll
    for (int s = 0; s < 2; s++) {
        const __half* p = Qs + (16*w + (lane&7) + 8*((lane>>3)&1))*KVP
                          + 16*s + 8*(lane>>4);
        LDSM4(qa[s], p);
    }

    float l0 = 0.f, l1 = 0.f;
    float o[4][4];
    unsigned oh[4][2];
    #pragma unroll
    for (int i = 0; i < 4; i++) {
        oh[i][0] = 0u; oh[i][1] = 0u;
        #pragma unroll
        for (int j = 0; j < 4; j++) o[i][j] = 0.f;
    }

    int r0 = 16*w + (lane>>2), r1 = r0 + 8;
    const unsigned* mg0 = g_adjbits + (size_t)(i0 + r0)*(NN/32);
    const unsigned* mg1 = g_adjbits + (size_t)(i0 + r1)*(NN/32);
    uint2 mk0 = *(const uint2*)mg0;
    uint2 mk1 = *(const uint2*)mg1;

    for (int jt = 0; jt < NN/64; jt++) {
        __half* cur = (jt & 1) ? KV1 : KV0;
        __half* nxt = (jt & 1) ? KV0 : KV1;
        if (jt < NN/64 - 1) {
            int j0n = (jt+1)*64;
            int r = t >> 2, c = (t & 3)*8;
            const __half* kb = K + ((size_t)(b*NN + j0n + r))*DD + h*HDIM + c;
            const __half* vb = V + ((size_t)(b*NN + j0n + r))*DD + h*HDIM + c;
            CPA16(nxt + r*KVP + c, kb);
            CPA16(nxt + 64*KVP + r*KVP + c, vb);
        }
        CPA_COMMIT();
        uint2 nmk0 = mk0, nmk1 = mk1;
        if (jt < NN/64 - 1) {
            nmk0 = *(const uint2*)(mg0 + 2*(jt+1));
            nmk1 = *(const uint2*)(mg1 + 2*(jt+1));
        }
        CPA_WAIT1();
        __syncthreads();

        __half* Ks = cur;
        __half* Vs = cur + 64*KVP;

        // S = Q K^T, f16 accumulators (Q pre-scaled by SCALE*log2e)
        unsigned sc2[8][2];
        #pragma unroll
        for (int nf = 0; nf < 8; nf++) {
            unsigned kb4[4];
            const __half* p = Ks + (8*nf + (lane&7))*KVP + 8*(lane>>3);
            LDSM4(kb4, p);
            sc2[nf][0] = 0u; sc2[nf][1] = 0u;
            mma16816hh(sc2[nf], qa[0], kb4[0], kb4[1]);
            mma16816hh(sc2[nf], qa[1], kb4[2], kb4[3]);
        }

        // mask (additive -inf, packed) + exp2; results are PV A-frags
        unsigned pex[8][2];
        __half2 la = __floats2half2_rn(0.f, 0.f), lb = la;
        #pragma unroll
        for (int nf = 0; nf < 8; nf++) {
            int sh = (8*nf + 2*(lane&3)) & 31;
            unsigned ua = (nf < 4) ? mk0.x : mk0.y;
            unsigned ub = (nf < 4) ? mk1.x : mk1.y;
            unsigned na = ~ua, nb = ~ub;
            unsigned m0 = ((na>>sh)&1u)*0xFC00u | ((na>>(sh+1))&1u)*0xFC000000u;
            unsigned m1 = ((nb>>sh)&1u)*0xFC00u | ((nb>>(sh+1))&1u)*0xFC000000u;
            __half2 s0 = __hadd2(*(__half2*)&sc2[nf][0], *(__half2*)&m0);
            __half2 s1 = __hadd2(*(__half2*)&sc2[nf][1], *(__half2*)&m1);
            unsigned e0 = ex2p(*(unsigned*)&s0);
            unsigned e1 = ex2p(*(unsigned*)&s1);
            pex[nf][0] = e0; pex[nf][1] = e1;
            la = __hadd2(la, *(__half2*)&e0);
            lb = __hadd2(lb, *(__half2*)&e1);
        }
        float2 fa = __half22float2(la), fb = __half22float2(lb);
        l0 += fa.x + fa.y;
        l1 += fb.x + fb.y;

        // O += P V, f16 accumulators
        #pragma unroll
        for (int ks = 0; ks < 4; ks++) {
            unsigned pa[4] = { pex[2*ks][0], pex[2*ks][1],
                               pex[2*ks+1][0], pex[2*ks+1][1] };
            #pragma unroll
            for (int np = 0; np < 2; np++) {
                unsigned vb4[4];
                const __half* p = Vs
                    + (16*ks + (lane&7) + 8*((lane>>3)&1))*KVP
                    + 16*np + 8*(lane>>4);
                LDSM4T(vb4, p);
                mma16816hh(oh[2*np],     pa, vb4[0], vb4[1]);
                mma16816hh(oh[2*np + 1], pa, vb4[2], vb4[3]);
            }
        }
        // flush f16 O-accumulators to f32 every 8 tiles (bounds rounding)
        if ((jt & 7) == 7) {
            #pragma unroll
            for (int i = 0; i < 4; i++) {
                float2 fx = __half22float2(*(__half2*)&oh[i][0]);
                float2 fy = __half22float2(*(__half2*)&oh[i][1]);
                o[i][0] += fx.x; o[i][1] += fx.y;
                o[i][2] += fy.x; o[i][3] += fy.y;
                oh[i][0] = 0u; oh[i][1] = 0u;
            }
        }
        __syncthreads();
        mk0 = nmk0; mk1 = nmk1;
    }

    l0 += __shfl_xor_sync(0xffffffffu, l0, 1);
    l0 += __shfl_xor_sync(0xffffffffu, l0, 2);
    l1 += __shfl_xor_sync(0xffffffffu, l1, 1);
    l1 += __shfl_xor_sync(0xffffffffu, l1, 2);
    float inv0 = 1.f / l0, inv1 = 1.f / l1;
    int gi0 = i0 + r0, gi1 = i0 + r1;
    #pragma unroll
    for (int nd = 0; nd < 4; nd++) {
        int col = h*HDIM + 8*nd + 2*(lane&3);
        *(unsigned*)&O[((size_t)(b*NN) + gi0)*DD + col] = packbf(o[nd][0]*inv0, o[nd][1]*inv0);
        *(unsigned*)&O[((size_t)(b*NN) + gi1)*DD + col] = packbf(o[nd][2]*inv1, o[nd][3]*inv1);
    }
}

// ---------------- launch ----------------
extern "C" void kernel_launch(void* const* d_in, const int* in_sizes, int n_in,
                              void* d_out, int out_size) {
    const float* x     = (const float*)d_in[0];
    const float* t_emb = (const float*)d_in[1];
    const int*   adj   = (const int*)  d_in[2];
    const float* Wt  = (const float*)d_in[3];
    const float* bt  = (const float*)d_in[4];
    const float* W1  = (const float*)d_in[5];
    const float* b1  = (const float*)d_in[6];
    const float* Wg  = (const float*)d_in[7];
    const float* bg  = (const float*)d_in[8];
    const float* W2  = (const float*)d_in[9];
    const float* b2  = (const float*)d_in[10];
    const float* Wq  = (const float*)d_in[11];
    const float* bq  = (const float*)d_in[12];
    const float* Wk  = (const float*)d_in[13];
    const float* bk  = (const float*)d_in[14];
    const float* Wv  = (const float*)d_in[15];
    const float* bv  = (const float*)d_in[16];
    const float* Wo  = (const float*)d_in[17];
    const float* bo  = (const float*)d_in[18];
    const float* g1  = (const float*)d_in[19];
    const float* be1 = (const float*)d_in[20];
    const float* g2  = (const float*)d_in[21];
    const float* be2 = (const float*)d_in[22];
    float* out = (float*)d_out;

    float *pX2;
    float *pTP;
    __nv_bfloat16 *pb1, *pb2, *pWB;
    __half *pq, *pk, *pv;
    cudaGetSymbolAddress((void**)&pTP, g_tparams);
    cudaGetSymbolAddress((void**)&pX2, g_x2);
    cudaGetSymbolAddress((void**)&pb1, g_bf1);
    cudaGetSymbolAddress((void**)&pb2, g_bf2);
    cudaGetSymbolAddress((void**)&pWB, g_wb);
    cudaGetSymbolAddress((void**)&pq,  g_q);
    cudaGetSymbolAddress((void**)&pk,  g_k);
    cudaGetSymbolAddress((void**)&pv,  g_v);

    cudaFuncSetAttribute(k_gemm_tc,  cudaFuncAttributeMaxDynamicSharedMemorySize, GEMM_TC_SMEM);
    cudaFuncSetAttribute(k_gemm_glu, cudaFuncAttributeMaxDynamicSharedMemorySize, GLU_SMEM);
    cudaFuncSetAttribute(k_attn,     cudaFuncAttributeMaxDynamicSharedMemorySize, ATTN_SMEM);

    // one fused pre-pass launch
    k_prep<<<2353, 256>>>(W1, Wg, b1, bg, W2, Wq, Wk, Wv, Wo, t_emb, Wt, bt, adj);
    // ln1 with FiLM -> bf16 (pb1)
    k_ln<<<M_ROWS/4, 128>>>(x, pTP, g1, be1, pb1);
    // h = glu(ln1 @ Wf + bf) -> bf16 (pb2)
    k_gemm_glu<<<256, 256, GLU_SMEM>>>(pb1, pb2);

    GArgs a;
    // x2 = x + h @ W2 + b2 -> fp32 (pX2)
    a = {pb2, pWB+OW2,0,0, b2,0,0, x, pX2, 0,0,0, 128, 0, 0, 1.f};
    k_gemm_tc<<<dim3(256,1), 256, GEMM_TC_SMEM>>>(a);
    // ln2 -> bf16 (pb1)
    k_ln<<<M_ROWS/4, 128>>>(pX2, nullptr, g2, be2, pb1);
    // q,k,v fused (grid.y = 3), f16 out; q pre-scaled by SCALE*log2e
    a = {pb1, pWB+OWQ,pWB+OWK,pWB+OWV, bq,bk,bv, 0, 0, pq,pk,pv, 128, 1, 1, EXC};
    k_gemm_tc<<<dim3(256,3), 256, GEMM_TC_SMEM>>>(a);
    // masked flash attention -> bf16 (pb1)
    k_attn<<<dim3(NN/128, HH, BB), 256, ATTN_SMEM>>>(pq, pk, pv, pb1);
    // out = x2 + attn @ Wo + bo -> fp32 d_out
    a = {pb1, pWB+OWO,0,0, bo,0,0, pX2, out, 0,0,0, 128, 0, 0, 1.f};
    k_gemm_tc<<<dim3(256,1), 256, GEMM_TC_SMEM>>>(a);
}